// round 14
// baseline (speedup 1.0000x reference)
#include <cuda_runtime.h>
#include <cuda_fp16.h>
#include <cstdint>

#define NN 64
#define CC 128
#define FF 2048
#define MM 128
typedef unsigned long long u64;

// softmax weights, split fp16 (hi + lo), [n][c][m]
__device__ __half g_Whi[(size_t)NN * CC * MM];
__device__ __half g_Wlo[(size_t)NN * CC * MM];
// partial scores [ksplit][c][n][m], fp32 (carry x256 scale)
__device__ float g_S[(size_t)2 * CC * NN * MM];

__device__ __forceinline__ uint32_t smem_u32(const void* p) {
    uint32_t a;
    asm("{ .reg .u64 t; cvta.to.shared.u64 t, %1; cvt.u32.u64 %0, t; }" : "=r"(a) : "l"(p));
    return a;
}
__device__ __forceinline__ void ldm_x4(uint32_t* r, uint32_t addr) {
    asm volatile("ldmatrix.sync.aligned.m8n8.x4.shared.b16 {%0,%1,%2,%3}, [%4];"
                 : "=r"(r[0]), "=r"(r[1]), "=r"(r[2]), "=r"(r[3]) : "r"(addr));
}
__device__ __forceinline__ void ldm_x4t(uint32_t* r, uint32_t addr) {
    asm volatile("ldmatrix.sync.aligned.m8n8.x4.trans.shared.b16 {%0,%1,%2,%3}, [%4];"
                 : "=r"(r[0]), "=r"(r[1]), "=r"(r[2]), "=r"(r[3]) : "r"(addr));
}
__device__ __forceinline__ void mma16816(float* d, const uint32_t* a,
                                         uint32_t b0, uint32_t b1) {
    asm volatile(
        "mma.sync.aligned.m16n8k16.row.col.f32.f16.f16.f32 "
        "{%0,%1,%2,%3}, {%4,%5,%6,%7}, {%8,%9}, {%0,%1,%2,%3};"
        : "+f"(d[0]), "+f"(d[1]), "+f"(d[2]), "+f"(d[3])
        : "r"(a[0]), "r"(a[1]), "r"(a[2]), "r"(a[3]), "r"(b0), "r"(b1));
}
__device__ __forceinline__ u64 cvt4h(const float4 v, float s) {
    __half2 h01 = __floats2half2_rn(v.x * s, v.y * s);
    __half2 h23 = __floats2half2_rn(v.z * s, v.w * s);
    return (u64)*(uint32_t*)&h01 | ((u64)*(uint32_t*)&h23 << 32);
}

#define ASCALE 256.0f
#define INV_ASCALE (1.0f / 256.0f)

// ============================================================================
// k1: grid (2 k-halves, 128 c), 256 thr, 2 CTAs/SM. Partial scores
// S[n=64, m=128] over K=1024 -> g_S[ksb][c][n][m] (fp32, x256 scale).
// fp16 single term, K chunks of 64, double-buffered smem (2 x 27648B):
// buffer: Ah@0 (128x144B) Xh@18432 (64x144B). Warp tile 16n x 64m.
// ============================================================================
__global__ __launch_bounds__(256, 2) void k1_scores(const float* __restrict__ X,
                                                    const float* __restrict__ A) {
    extern __shared__ __align__(16) char sm1[];
    const uint32_t sB = smem_u32(sm1);
    const int tid = threadIdx.x, w = tid >> 5, lane = tid & 31;
    const int ksb = blockIdx.x, c = blockIdx.y;
    const int nb = w & 3, mb = w >> 2;

    const int ar = tid >> 1, ah = tid & 1;   // A: row m, 32-float half of 64k
    const int xr = tid >> 2, xq = tid & 3;   // X: row n, 16-float quarter
    const float* Arow = A + ((size_t)c * MM + ar) * FF + ksb * 1024 + ah * 32;
    const float* Xrow = X + ((size_t)xr * CC + c) * FF + ksb * 1024 + xq * 16;

    const uint32_t xfrow = nb * 16 + (lane & 7) + ((lane >> 3) & 1) * 8;
    const uint32_t xfoff = 18432 + xfrow * 144 + ((lane >> 4) & 1) * 16;
    const uint32_t afrow = mb * 64 + (lane & 7) + ((lane >> 4) & 1) * 8;
    const uint32_t afoff = afrow * 144 + ((lane >> 3) & 1) * 16;

    float d[8][4];
#pragma unroll
    for (int t = 0; t < 8; t++)
#pragma unroll
        for (int i = 0; i < 4; i++) d[t][i] = 0.f;

    float4 ra[8], rx[4];
#pragma unroll
    for (int i = 0; i < 8; i++) ra[i] = *(const float4*)(Arow + i * 4);
#pragma unroll
    for (int i = 0; i < 4; i++) rx[i] = *(const float4*)(Xrow + i * 4);
#pragma unroll
    for (int i = 0; i < 8; i++)
        *(u64*)(sm1 + (uint32_t)(ar * 144 + ah * 64 + i * 8)) = cvt4h(ra[i], ASCALE);
#pragma unroll
    for (int i = 0; i < 4; i++)
        *(u64*)(sm1 + 18432 + (uint32_t)(xr * 144 + xq * 32 + i * 8)) = cvt4h(rx[i], 1.f);
#pragma unroll
    for (int i = 0; i < 8; i++) ra[i] = *(const float4*)(Arow + 64 + i * 4);
#pragma unroll
    for (int i = 0; i < 4; i++) rx[i] = *(const float4*)(Xrow + 64 + i * 4);
    __syncthreads();

    for (int ch = 0; ch < 16; ch++) {
        const int b = ch & 1;
        char* nbuf = sm1 + (b ^ 1) * 27648;
        if (ch < 15) {
#pragma unroll
            for (int i = 0; i < 8; i++)
                *(u64*)(nbuf + (uint32_t)(ar * 144 + ah * 64 + i * 8)) = cvt4h(ra[i], ASCALE);
#pragma unroll
            for (int i = 0; i < 4; i++)
                *(u64*)(nbuf + 18432 + (uint32_t)(xr * 144 + xq * 32 + i * 8)) = cvt4h(rx[i], 1.f);
        }
        if (ch < 14) {
            const int k0 = (ch + 2) * 64;
#pragma unroll
            for (int i = 0; i < 8; i++) ra[i] = *(const float4*)(Arow + k0 + i * 4);
#pragma unroll
            for (int i = 0; i < 4; i++) rx[i] = *(const float4*)(Xrow + k0 + i * 4);
        }
        const uint32_t B = sB + b * 27648;
#pragma unroll
        for (int ks = 0; ks < 4; ks++) {
            uint32_t xh[4], ahf[16];
            ldm_x4(xh, B + xfoff + ks * 32);
#pragma unroll
            for (int p = 0; p < 4; p++) ldm_x4(ahf + p * 4, B + afoff + p * 2304 + ks * 32);
#pragma unroll
            for (int t = 0; t < 8; t++) mma16816(d[t], xh, ahf[t * 2], ahf[t * 2 + 1]);
        }
        __syncthreads();
    }

    // write partial scores (fp32, still x256-scaled)
    float* Sp = g_S + (size_t)(ksb * CC + c) * (NN * MM);
    const int r0 = nb * 16 + (lane >> 2);
#pragma unroll
    for (int t = 0; t < 8; t++) {
        const int mcol = mb * 64 + t * 8 + (lane & 3) * 2;
        *(float2*)(Sp + r0 * MM + mcol)       = make_float2(d[t][0], d[t][1]);
        *(float2*)(Sp + (r0 + 8) * MM + mcol) = make_float2(d[t][2], d[t][3]);
    }
}

// ============================================================================
// k1b: sum the two K-partials, softmax over m, emit split fp16 Whi/Wlo.
// 8192 rows (c,n); 8 threads/row; grid 256 x 256 thr (32 rows/block).
// ============================================================================
__global__ __launch_bounds__(256) void k1b_softmax() {
    const int tid = threadIdx.x;
    const int R = blockIdx.x * 32 + (tid >> 3);   // linear over [c][n]
    const int q = tid & 7;
    const int c = R >> 6, n = R & 63;

    const float* s0 = g_S + (size_t)R * MM + q * 16;
    const float* s1 = s0 + (size_t)CC * NN * MM;
    float v[16];
#pragma unroll
    for (int i = 0; i < 4; i++) {
        float4 a = *(const float4*)(s0 + i * 4);
        float4 b = *(const float4*)(s1 + i * 4);
        v[i * 4 + 0] = (a.x + b.x) * INV_ASCALE;
        v[i * 4 + 1] = (a.y + b.y) * INV_ASCALE;
        v[i * 4 + 2] = (a.z + b.z) * INV_ASCALE;
        v[i * 4 + 3] = (a.w + b.w) * INV_ASCALE;
    }
    float mx = v[0];
#pragma unroll
    for (int i = 1; i < 16; i++) mx = fmaxf(mx, v[i]);
    mx = fmaxf(mx, __shfl_xor_sync(0xffffffffu, mx, 1));
    mx = fmaxf(mx, __shfl_xor_sync(0xffffffffu, mx, 2));
    mx = fmaxf(mx, __shfl_xor_sync(0xffffffffu, mx, 4));
    float sum = 0.f;
#pragma unroll
    for (int i = 0; i < 16; i++) { v[i] = __expf(v[i] - mx); sum += v[i]; }
    sum += __shfl_xor_sync(0xffffffffu, sum, 1);
    sum += __shfl_xor_sync(0xffffffffu, sum, 2);
    sum += __shfl_xor_sync(0xffffffffu, sum, 4);
    const float inv = 1.f / sum;

    __half* whi = g_Whi + ((size_t)n * CC + c) * MM + q * 16;
    __half* wlo = g_Wlo + ((size_t)n * CC + c) * MM + q * 16;
#pragma unroll
    for (int m = 0; m < 16; m += 2) {
        float w0 = v[m] * inv, w1 = v[m + 1] * inv;
        __half2 h = __floats2half2_rn(w0, w1);
        float2 hf = __half22float2(h);
        __half2 l = __floats2half2_rn(w0 - hf.x, w1 - hf.y);
        *(__half2*)(whi + m) = h;
        *(__half2*)(wlo + m) = l;
    }
}

// ============================================================================
// k2: grid (4 f-quarters, 64 n), 256 thr, 2 CTAs/SM. out = (Whi+Wlo)*Xfp16.
// smem 71680: Wlo @0 (persistent, pitch 272, 34816B);
//             X bufs @34816 / @53248 (18432B each, pitch 144).
// Whi staged temporarily @34816, preloaded to regs (wh[32]), then overwritten.
// Warp tile 16c x 64f; 8 tiles of 64f; one sync/tile; X prefetch depth 1.
// ============================================================================
__global__ __launch_bounds__(256, 2) void k2_combine(const float* __restrict__ X,
                                                     float* __restrict__ Out) {
    extern __shared__ __align__(16) char sm2[];
    const uint32_t sB = smem_u32(sm2);
    const int tid = threadIdx.x, w = tid >> 5, lane = tid & 31;
    const int n = blockIdx.y, fh = blockIdx.x;

    const int cr = tid >> 1, hh = tid & 1;
    {   // stage Wlo (persistent @0) and Whi (temp @34816)
        const __half* WhiG = g_Whi + ((size_t)n * CC + cr) * MM + hh * 64;
        const __half* WloG = g_Wlo + ((size_t)n * CC + cr) * MM + hh * 64;
#pragma unroll
        for (int i = 0; i < 16; i++) {
            const uint32_t o = (uint32_t)(cr * 272 + hh * 128 + i * 8);
            *(u64*)(sm2 + o)         = *(const u64*)(WloG + i * 4);
            *(u64*)(sm2 + 34816 + o) = *(const u64*)(WhiG + i * 4);
        }
    }
    __syncthreads();
    const uint32_t wrow = w * 16 + (lane & 7) + ((lane >> 3) & 1) * 8;
    const uint32_t wboff = wrow * 272 + ((lane >> 4) & 1) * 16;
    uint32_t wh[32];
#pragma unroll
    for (int ks = 0; ks < 8; ks++) ldm_x4(wh + ks * 4, sB + 34816 + wboff + ks * 32);
    __syncthreads();   // Whi consumed; @34816 becomes X buffer space

    const uint32_t xmrow = (lane & 7) + ((lane >> 3) & 1) * 8;
    const uint32_t xboff = xmrow * 144 + ((lane >> 4) & 1) * 16;
    const float* Xrow2 = X + ((size_t)n * CC + cr) * FF + fh * 512 + hh * 32;
    float* Ob = Out + ((size_t)n * CC) * FF + fh * 512;

    float4 rx[8];
#pragma unroll
    for (int i = 0; i < 8; i++) rx[i] = *(const float4*)(Xrow2 + i * 4);
#pragma unroll
    for (int i = 0; i < 8; i++)
        *(u64*)(sm2 + 34816 + (uint32_t)(cr * 144 + hh * 64 + i * 8)) = cvt4h(rx[i], 1.f);
#pragma unroll
    for (int i = 0; i < 8; i++) rx[i] = *(const float4*)(Xrow2 + 64 + i * 4);
    __syncthreads();

    for (int t = 0; t < 8; t++) {
        const int b = t & 1;
        char* nbuf = sm2 + 34816 + (b ^ 1) * 18432;
        if (t < 7) {   // stage tile t+1
#pragma unroll
            for (int i = 0; i < 8; i++)
                *(u64*)(nbuf + (uint32_t)(cr * 144 + hh * 64 + i * 8)) = cvt4h(rx[i], 1.f);
        }
        if (t < 6) {   // LDG tile t+2
#pragma unroll
            for (int i = 0; i < 8; i++)
                rx[i] = *(const float4*)(Xrow2 + (t + 2) * 64 + i * 4);
        }

        float d[8][4];
#pragma unroll
        for (int ft = 0; ft < 8; ft++)
#pragma unroll
            for (int i = 0; i < 4; i++) d[ft][i] = 0.f;

        const uint32_t B = sB + 34816 + b * 18432;
#pragma unroll
        for (int ks = 0; ks < 8; ks++) {
            uint32_t wlf[4], xh[8];
            ldm_x4(wlf, sB + wboff + ks * 32);   // Wlo frag from persistent smem
            ldm_x4t(xh,     B + xboff + ks * 2304);
            ldm_x4t(xh + 4, B + xboff + ks * 2304 + 32);
#pragma unroll
            for (int ft = 0; ft < 4; ft++) {
                mma16816(d[ft], wh + ks * 4, xh[ft * 2], xh[ft * 2 + 1]);
                mma16816(d[ft], wlf,         xh[ft * 2], xh[ft * 2 + 1]);
            }
            ldm_x4t(xh,     B + xboff + ks * 2304 + 64);
            ldm_x4t(xh + 4, B + xboff + ks * 2304 + 96);
#pragma unroll
            for (int ft = 0; ft < 4; ft++) {
                mma16816(d[4 + ft], wh + ks * 4, xh[ft * 2], xh[ft * 2 + 1]);
                mma16816(d[4 + ft], wlf,         xh[ft * 2], xh[ft * 2 + 1]);
            }
        }

        const int crow = w * 16 + (lane >> 2);
#pragma unroll
        for (int ft = 0; ft < 8; ft++) {
            const int f = t * 64 + ft * 8 + (lane & 3) * 2;
            *(float2*)(Ob + (size_t)crow * FF + f)       = make_float2(d[ft][0], d[ft][1]);
            *(float2*)(Ob + (size_t)(crow + 8) * FF + f) = make_float2(d[ft][2], d[ft][3]);
        }
        __syncthreads();
    }
}

extern "C" void kernel_launch(void* const* d_in, const int* in_sizes, int n_in,
                              void* d_out, int out_size) {
    const float* X = (const float*)d_in[0];
    const float* A = (const float*)d_in[1];
    float* Out = (float*)d_out;

    cudaFuncSetAttribute(k1_scores, cudaFuncAttributeMaxDynamicSharedMemorySize, 55296);
    cudaFuncSetAttribute(k2_combine, cudaFuncAttributeMaxDynamicSharedMemorySize, 71680);

    dim3 g1(2, CC);
    k1_scores<<<g1, 256, 55296>>>(X, A);
    k1b_softmax<<<256, 256>>>();
    dim3 g2(4, NN);
    k2_combine<<<g2, 256, 71680>>>(X, Out);
}

// round 16
// speedup vs baseline: 1.1494x; 1.1494x over previous
#include <cuda_runtime.h>
#include <cuda_fp16.h>
#include <cstdint>

#define NN 64
#define CC 128
#define FF 2048
#define MM 128
typedef unsigned long long u64;

// partial scores [ksplit][c][n][m], fp32 (carry x256 scale)
__device__ float g_S[(size_t)2 * CC * NN * MM];

__device__ __forceinline__ uint32_t smem_u32(const void* p) {
    uint32_t a;
    asm("{ .reg .u64 t; cvta.to.shared.u64 t, %1; cvt.u32.u64 %0, t; }" : "=r"(a) : "l"(p));
    return a;
}
__device__ __forceinline__ void ldm_x4(uint32_t* r, uint32_t addr) {
    asm volatile("ldmatrix.sync.aligned.m8n8.x4.shared.b16 {%0,%1,%2,%3}, [%4];"
                 : "=r"(r[0]), "=r"(r[1]), "=r"(r[2]), "=r"(r[3]) : "r"(addr));
}
__device__ __forceinline__ void ldm_x4t(uint32_t* r, uint32_t addr) {
    asm volatile("ldmatrix.sync.aligned.m8n8.x4.trans.shared.b16 {%0,%1,%2,%3}, [%4];"
                 : "=r"(r[0]), "=r"(r[1]), "=r"(r[2]), "=r"(r[3]) : "r"(addr));
}
__device__ __forceinline__ void mma16816(float* d, const uint32_t* a,
                                         uint32_t b0, uint32_t b1) {
    asm volatile(
        "mma.sync.aligned.m16n8k16.row.col.f32.f16.f16.f32 "
        "{%0,%1,%2,%3}, {%4,%5,%6,%7}, {%8,%9}, {%0,%1,%2,%3};"
        : "+f"(d[0]), "+f"(d[1]), "+f"(d[2]), "+f"(d[3])
        : "r"(a[0]), "r"(a[1]), "r"(a[2]), "r"(a[3]), "r"(b0), "r"(b1));
}
__device__ __forceinline__ u64 cvt4h(const float4 v, float s) {
    __half2 h01 = __floats2half2_rn(v.x * s, v.y * s);
    __half2 h23 = __floats2half2_rn(v.z * s, v.w * s);
    return (u64)*(uint32_t*)&h01 | ((u64)*(uint32_t*)&h23 << 32);
}

#define ASCALE 256.0f
#define INV_ASCALE (1.0f / 256.0f)

// ============================================================================
// k1: grid (2 k-halves, 128 c), 256 thr, 2 CTAs/SM. Partial scores
// S[n=64, m=128] over K=1024 -> g_S[ksb][c][n][m] (fp32, x256 scale).
// fp16 single term, K chunks of 64, double-buffered smem (2 x 27648B):
// buffer: Ah@0 (128x144B) Xh@18432 (64x144B).
// Warp tile 32n x 32m (nb = w&1, mb = w>>1): dup-optimal ldmatrix traffic
// (A frags x2, X frags x4 -> 64KB LDS/chunk vs 80KB for 16x64).
// ============================================================================
__global__ __launch_bounds__(256, 2) void k1_scores(const float* __restrict__ X,
                                                    const float* __restrict__ A) {
    extern __shared__ __align__(16) char sm1[];
    const uint32_t sB = smem_u32(sm1);
    const int tid = threadIdx.x, w = tid >> 5, lane = tid & 31;
    const int ksb = blockIdx.x, c = blockIdx.y;
    const int nb = w & 1, mb = w >> 1;

    const int ar = tid >> 1, ah = tid & 1;   // A: row m, 32-float half of 64k
    const int xr = tid >> 2, xq = tid & 3;   // X: row n, 16-float quarter
    const float* Arow = A + ((size_t)c * MM + ar) * FF + ksb * 1024 + ah * 32;
    const float* Xrow = X + ((size_t)xr * CC + c) * FF + ksb * 1024 + xq * 16;

    // fragment bases: X a-frags (two 16n subtiles), A b-frags (two ldm.x4 = 32m)
    const uint32_t xfr0 = nb * 32 + (lane & 7) + ((lane >> 3) & 1) * 8;
    const uint32_t xfoff0 = 18432 + xfr0 * 144 + ((lane >> 4) & 1) * 16;        // sub 0
    const uint32_t xfoff1 = xfoff0 + 16 * 144;                                  // sub 1
    const uint32_t afrow = mb * 32 + (lane & 7) + ((lane >> 4) & 1) * 8;
    const uint32_t afoff = afrow * 144 + ((lane >> 3) & 1) * 16;

    float d[8][4];   // [sub(2) x mtile(4)]
#pragma unroll
    for (int t = 0; t < 8; t++)
#pragma unroll
        for (int i = 0; i < 4; i++) d[t][i] = 0.f;

    float4 ra[8], rx[4];
#pragma unroll
    for (int i = 0; i < 8; i++) ra[i] = *(const float4*)(Arow + i * 4);
#pragma unroll
    for (int i = 0; i < 4; i++) rx[i] = *(const float4*)(Xrow + i * 4);
#pragma unroll
    for (int i = 0; i < 8; i++)
        *(u64*)(sm1 + (uint32_t)(ar * 144 + ah * 64 + i * 8)) = cvt4h(ra[i], ASCALE);
#pragma unroll
    for (int i = 0; i < 4; i++)
        *(u64*)(sm1 + 18432 + (uint32_t)(xr * 144 + xq * 32 + i * 8)) = cvt4h(rx[i], 1.f);
#pragma unroll
    for (int i = 0; i < 8; i++) ra[i] = *(const float4*)(Arow + 64 + i * 4);
#pragma unroll
    for (int i = 0; i < 4; i++) rx[i] = *(const float4*)(Xrow + 64 + i * 4);
    __syncthreads();

    for (int ch = 0; ch < 16; ch++) {
        const int b = ch & 1;
        char* nbuf = sm1 + (b ^ 1) * 27648;
        if (ch < 15) {
#pragma unroll
            for (int i = 0; i < 8; i++)
                *(u64*)(nbuf + (uint32_t)(ar * 144 + ah * 64 + i * 8)) = cvt4h(ra[i], ASCALE);
#pragma unroll
            for (int i = 0; i < 4; i++)
                *(u64*)(nbuf + 18432 + (uint32_t)(xr * 144 + xq * 32 + i * 8)) = cvt4h(rx[i], 1.f);
        }
        if (ch < 14) {
            const int k0 = (ch + 2) * 64;
#pragma unroll
            for (int i = 0; i < 8; i++) ra[i] = *(const float4*)(Arow + k0 + i * 4);
#pragma unroll
            for (int i = 0; i < 4; i++) rx[i] = *(const float4*)(Xrow + k0 + i * 4);
        }
        const uint32_t B = sB + b * 27648;
#pragma unroll
        for (int ks = 0; ks < 4; ks++) {
            uint32_t xh0[4], xh1[4], ahf[8];
            ldm_x4(xh0, B + xfoff0 + ks * 32);
            ldm_x4(xh1, B + xfoff1 + ks * 32);
            ldm_x4(ahf,     B + afoff + ks * 32);            // m-tiles 0,1
            ldm_x4(ahf + 4, B + afoff + 2304 + ks * 32);     // m-tiles 2,3
#pragma unroll
            for (int t = 0; t < 4; t++) mma16816(d[t],     xh0, ahf[t * 2], ahf[t * 2 + 1]);
#pragma unroll
            for (int t = 0; t < 4; t++) mma16816(d[4 + t], xh1, ahf[t * 2], ahf[t * 2 + 1]);
        }
        __syncthreads();
    }

    // write partial scores (fp32, still x256-scaled)
    float* Sp = g_S + (size_t)(ksb * CC + c) * (NN * MM);
#pragma unroll
    for (int sub = 0; sub < 2; sub++) {
        const int r0 = nb * 32 + sub * 16 + (lane >> 2);
#pragma unroll
        for (int t = 0; t < 4; t++) {
            const int mcol = mb * 32 + t * 8 + (lane & 3) * 2;
            *(float2*)(Sp + r0 * MM + mcol)       = make_float2(d[sub * 4 + t][0], d[sub * 4 + t][1]);
            *(float2*)(Sp + (r0 + 8) * MM + mcol) = make_float2(d[sub * 4 + t][2], d[sub * 4 + t][3]);
        }
    }
}

// ============================================================================
// k2: grid (2 f-halves, 64 n), 256 thr. out[c,f] = sum_m W[n,c,m]*X[n,m,f].
// PROLOGUE: fused softmax — read g_S partials for this n (2 thr/row, 128 rows),
// softmax over m, write split fp16 Whi/Wlo into smem stage (pitch 272:
// Whi@0, Wlo@34816), preload W fragments to registers (R12-proven mainloop).
// X tiles [m=128][f=64] fp16 double-buffered (pitch 144, 18432B each).
// ============================================================================
__global__ __launch_bounds__(256, 1) void k2_combine(const float* __restrict__ X,
                                                     float* __restrict__ Out) {
    extern __shared__ __align__(16) char sm2[];
    const uint32_t sB = smem_u32(sm2);
    const int tid = threadIdx.x, w = tid >> 5, lane = tid & 31;
    const int n = blockIdx.y, fh = blockIdx.x;

    const int cr = tid >> 1, hh = tid & 1;
    // ---- fused softmax prologue: g_S -> split W in smem ----
    {
        const float* s0 = g_S + ((size_t)cr * NN + n) * MM + hh * 64;
        const float* s1 = s0 + (size_t)CC * NN * MM;
        float v[64];
#pragma unroll
        for (int i = 0; i < 16; i++) {
            float4 a = *(const float4*)(s0 + i * 4);
            float4 b = *(const float4*)(s1 + i * 4);
            v[i * 4 + 0] = (a.x + b.x) * INV_ASCALE;
            v[i * 4 + 1] = (a.y + b.y) * INV_ASCALE;
            v[i * 4 + 2] = (a.z + b.z) * INV_ASCALE;
            v[i * 4 + 3] = (a.w + b.w) * INV_ASCALE;
        }
        float mx = v[0];
#pragma unroll
        for (int i = 1; i < 64; i++) mx = fmaxf(mx, v[i]);
        mx = fmaxf(mx, __shfl_xor_sync(0xffffffffu, mx, 1));
        float sum = 0.f;
#pragma unroll
        for (int i = 0; i < 64; i++) { v[i] = __expf(v[i] - mx); sum += v[i]; }
        sum += __shfl_xor_sync(0xffffffffu, sum, 1);
        const float inv = 1.f / sum;
#pragma unroll
        for (int i = 0; i < 32; i++) {
            float w0 = v[i * 2] * inv, w1 = v[i * 2 + 1] * inv;
            __half2 h = __floats2half2_rn(w0, w1);
            float2 hf = __half22float2(h);
            __half2 l = __floats2half2_rn(w0 - hf.x, w1 - hf.y);
            const uint32_t o = (uint32_t)(cr * 272 + hh * 128 + i * 4);
            *(uint32_t*)(sm2 + o)         = *(uint32_t*)&h;
            *(uint32_t*)(sm2 + 34816 + o) = *(uint32_t*)&l;
        }
    }
    __syncthreads();
    uint32_t wh[32], wl[32];
    {
        const uint32_t wrow = w * 16 + (lane & 7) + ((lane >> 3) & 1) * 8;
        const uint32_t wboff = wrow * 272 + ((lane >> 4) & 1) * 16;
#pragma unroll
        for (int ks = 0; ks < 8; ks++) {
            ldm_x4(wh + ks * 4, sB + wboff + ks * 32);
            ldm_x4(wl + ks * 4, sB + 34816 + wboff + ks * 32);
        }
    }
    __syncthreads();   // W in regs; smem free for X buffers

    const uint32_t xmrow = (lane & 7) + ((lane >> 3) & 1) * 8;
    const uint32_t xboff = xmrow * 144 + ((lane >> 4) & 1) * 16;
    const float* Xrow2 = X + ((size_t)n * CC + cr) * FF + fh * 1024 + hh * 32;
    float* Ob = Out + ((size_t)n * CC) * FF + fh * 1024;

    float4 rx[8];
#pragma unroll
    for (int i = 0; i < 8; i++) rx[i] = *(const float4*)(Xrow2 + i * 4);
#pragma unroll
    for (int i = 0; i < 8; i++)
        *(u64*)(sm2 + (uint32_t)(cr * 144 + hh * 64 + i * 8)) = cvt4h(rx[i], 1.f);
#pragma unroll
    for (int i = 0; i < 8; i++) rx[i] = *(const float4*)(Xrow2 + 64 + i * 4);
    __syncthreads();

    for (int t = 0; t < 16; t++) {
        const int b = t & 1;
        char* nbuf = sm2 + (b ^ 1) * 18432;
        if (t < 15) {   // stage tile t+1
#pragma unroll
            for (int i = 0; i < 8; i++)
                *(u64*)(nbuf + (uint32_t)(cr * 144 + hh * 64 + i * 8)) = cvt4h(rx[i], 1.f);
        }
        if (t < 14) {   // LDG tile t+2
#pragma unroll
            for (int i = 0; i < 8; i++)
                rx[i] = *(const float4*)(Xrow2 + (t + 2) * 64 + i * 4);
        }

        float d[8][4];
#pragma unroll
        for (int ft = 0; ft < 8; ft++)
#pragma unroll
            for (int i = 0; i < 4; i++) d[ft][i] = 0.f;

        const uint32_t B = sB + b * 18432;
#pragma unroll
        for (int ks = 0; ks < 8; ks++) {
            uint32_t xh[16];
#pragma unroll
            for (int j = 0; j < 4; j++) ldm_x4t(xh + j * 4, B + xboff + ks * 2304 + j * 32);
#pragma unroll
            for (int ft = 0; ft < 8; ft++) mma16816(d[ft], wh + ks * 4, xh[ft * 2], xh[ft * 2 + 1]);
#pragma unroll
            for (int ft = 0; ft < 8; ft++) mma16816(d[ft], wl + ks * 4, xh[ft * 2], xh[ft * 2 + 1]);
        }

        const int crow = w * 16 + (lane >> 2);
#pragma unroll
        for (int ft = 0; ft < 8; ft++) {
            const int f = t * 64 + ft * 8 + (lane & 3) * 2;
            *(float2*)(Ob + (size_t)crow * FF + f)       = make_float2(d[ft][0], d[ft][1]);
            *(float2*)(Ob + (size_t)(crow + 8) * FF + f) = make_float2(d[ft][2], d[ft][3]);
        }
        __syncthreads();
    }
}

extern "C" void kernel_launch(void* const* d_in, const int* in_sizes, int n_in,
                              void* d_out, int out_size) {
    const float* X = (const float*)d_in[0];
    const float* A = (const float*)d_in[1];
    float* Out = (float*)d_out;

    cudaFuncSetAttribute(k1_scores, cudaFuncAttributeMaxDynamicSharedMemorySize, 55296);
    cudaFuncSetAttribute(k2_combine, cudaFuncAttributeMaxDynamicSharedMemorySize, 69632);

    dim3 g1(2, CC);
    k1_scores<<<g1, 256, 55296>>>(X, A);
    dim3 g2(2, NN);
    k2_combine<<<g2, 256, 69632>>>(X, Out);
}